// round 1
// baseline (speedup 1.0000x reference)
#include <cuda_runtime.h>
#include <cstdint>

// Problem sizes (fixed by the dataset)
constexpr int M = 1024;     // batch
constexpr int N = 32768;    // gallery
constexpr int K = 512;      // embedding dim
constexpr float MARGIN = 0.3f;

// GEMM tiling
constexpr int BM = 128, BN = 128, BK = 16;

// Scratch: per-row hardest-positive (min sim) and hardest-negative (max sim)
__device__ float g_pos[M];
__device__ float g_neg[M];

__device__ __forceinline__ float f_inf()  { return __int_as_float(0x7f800000); }
__device__ __forceinline__ float f_ninf() { return __int_as_float(0xff800000); }

// Monotonic-int float atomics (work on shared and global generic pointers).
__device__ __forceinline__ void atomicMinF(float* a, float v) {
    if (v >= 0.f) atomicMin((int*)a, __float_as_int(v));
    else          atomicMax((unsigned int*)a, __float_as_uint(v));
}
__device__ __forceinline__ void atomicMaxF(float* a, float v) {
    if (v >= 0.f) atomicMax((int*)a, __float_as_int(v));
    else          atomicMin((unsigned int*)a, __float_as_uint(v));
}

__global__ void tl_init() {
    int i = blockIdx.x * 256 + threadIdx.x;
    if (i < M) { g_pos[i] = f_inf(); g_neg[i] = f_ninf(); }
}

// Fused SGEMM + masked min/max epilogue.
// A: [M,K] inputs, B: [N,K] features (sim = A @ B^T)
__global__ __launch_bounds__(256, 2)
void tl_gemm(const float* __restrict__ A, const float* __restrict__ B,
             const int* __restrict__ targets, const int* __restrict__ idxv,
             const int* __restrict__ labels)
{
    __shared__ float As[2][BK][BM];
    __shared__ float Bs[2][BK][BN];
    __shared__ float sPos[BM];
    __shared__ float sNeg[BM];

    const int tid = threadIdx.x;
    const int bx = blockIdx.x;              // gallery tile
    const int by = blockIdx.y;              // batch tile
    const int rowBase = by * BM;
    const int colBase = bx * BN;

    for (int i = tid; i < BM; i += 256) { sPos[i] = f_inf(); sNeg[i] = f_ninf(); }

    float acc[8][8] = {};

    // Loader: 256 threads fetch 128 rows x 16 k of both A and B tiles via float4.
    // v in [0,512): row = v>>2, k-quad = (v&3)*4  -> 64B contiguous per row.
    auto load = [&](int buf, int kBase) {
#pragma unroll
        for (int it = 0; it < 2; ++it) {
            int v  = tid + it * 256;
            int r  = v >> 2;
            int kq = (v & 3) * 4;
            float4 a = *reinterpret_cast<const float4*>(&A[(size_t)(rowBase + r) * K + kBase + kq]);
            As[buf][kq + 0][r] = a.x; As[buf][kq + 1][r] = a.y;
            As[buf][kq + 2][r] = a.z; As[buf][kq + 3][r] = a.w;
            float4 b = *reinterpret_cast<const float4*>(&B[(size_t)(colBase + r) * K + kBase + kq]);
            Bs[buf][kq + 0][r] = b.x; Bs[buf][kq + 1][r] = b.y;
            Bs[buf][kq + 2][r] = b.z; Bs[buf][kq + 3][r] = b.w;
        }
    };

    load(0, 0);
    __syncthreads();

    const int tx = tid & 15;        // 16 col-threads
    const int ty = tid >> 4;        // 16 row-threads
    const int rOff = ty * 8;
    const int cOff = tx * 8;

    int buf = 0;
    for (int kb = 0; kb < K; kb += BK) {
        if (kb + BK < K) load(buf ^ 1, kb + BK);
#pragma unroll
        for (int k = 0; k < BK; ++k) {
            float ra[8], rb[8];
            *(float4*)&ra[0] = *(const float4*)&As[buf][k][rOff];
            *(float4*)&ra[4] = *(const float4*)&As[buf][k][rOff + 4];
            *(float4*)&rb[0] = *(const float4*)&Bs[buf][k][cOff];
            *(float4*)&rb[4] = *(const float4*)&Bs[buf][k][cOff + 4];
#pragma unroll
            for (int i = 0; i < 8; ++i)
#pragma unroll
                for (int j = 0; j < 8; ++j)
                    acc[i][j] = fmaf(ra[i], rb[j], acc[i][j]);
        }
        __syncthreads();
        buf ^= 1;
    }

    // Epilogue: masked min/max per row of my 8x8 microtile.
    int lab[8];
#pragma unroll
    for (int j = 0; j < 8; ++j) lab[j] = labels[colBase + cOff + j];

#pragma unroll
    for (int i = 0; i < 8; ++i) {
        const int row = rowBase + rOff + i;
        const int t   = targets[row];
        const int ix  = idxv[row];
        float pmin = f_inf(), nmax = f_ninf();
#pragma unroll
        for (int j = 0; j < 8; ++j) {
            const int col = colBase + cOff + j;
            const float s = acc[i][j];
            const bool same = (lab[j] == t);
            if (same) {
                if (col != ix) pmin = fminf(pmin, s);
            } else {
                nmax = fmaxf(nmax, s);
            }
        }
        if (pmin <  f_inf())  atomicMinF(&sPos[rOff + i], pmin);
        if (nmax > f_ninf())  atomicMaxF(&sNeg[rOff + i], nmax);
    }
    __syncthreads();

    for (int i = tid; i < BM; i += 256) {
        const float p = sPos[i], q = sNeg[i];
        if (p <  f_inf())  atomicMinF(&g_pos[rowBase + i], p);
        if (q > f_ninf())  atomicMaxF(&g_neg[rowBase + i], q);
    }
}

// Final: loss_i = max(neg_i - pos_i + margin, 0); out = mean(loss)
__global__ void tl_final(float* __restrict__ out) {
    __shared__ float red[32];
    const int i = threadIdx.x;           // 1024 threads, one per row
    float l = g_neg[i] - g_pos[i] + MARGIN;   // -inf if either side empty
    l = fmaxf(l, 0.0f);
#pragma unroll
    for (int o = 16; o > 0; o >>= 1) l += __shfl_xor_sync(0xffffffffu, l, o);
    if ((i & 31) == 0) red[i >> 5] = l;
    __syncthreads();
    if (i < 32) {
        float s = red[i];
#pragma unroll
        for (int o = 16; o > 0; o >>= 1) s += __shfl_xor_sync(0xffffffffu, s, o);
        if (i == 0) out[0] = s * (1.0f / (float)M);
    }
}

extern "C" void kernel_launch(void* const* d_in, const int* in_sizes, int n_in,
                              void* d_out, int out_size) {
    const float* A       = (const float*)d_in[0];   // inputs   [1024,512]
    const float* B       = (const float*)d_in[1];   // features [32768,512]
    const int*   targets = (const int*)  d_in[2];   // [1024]
    const int*   idxv    = (const int*)  d_in[3];   // [1024]
    const int*   labels  = (const int*)  d_in[4];   // [32768]
    float*       out     = (float*)d_out;

    tl_init<<<(M + 255) / 256, 256>>>();
    dim3 grid(N / BN, M / BM);   // 256 x 8 = 2048 CTAs
    tl_gemm<<<grid, 256>>>(A, B, targets, idxv, labels);
    tl_final<<<1, M>>>(out);
}

// round 3
// speedup vs baseline: 5.5139x; 5.5139x over previous
#include <cuda_runtime.h>
#include <cuda_bf16.h>
#include <cstdint>

constexpr int M = 1024;
constexpr int N = 32768;
constexpr int K = 512;
constexpr float MARGIN = 0.3f;

constexpr int BM = 128, BN = 128, BK = 32;
constexpr int NCH = K / BK;           // 16 k-chunks
constexpr int LDS_STRIDE = 40;        // 32 + 8 pad (80B rows, conflict-free ldmatrix)

__device__ float g_pos[M];
__device__ float g_neg[M];

__device__ __forceinline__ float f_inf()  { return __int_as_float(0x7f800000); }
__device__ __forceinline__ float f_ninf() { return __int_as_float(0xff800000); }

__device__ __forceinline__ void atomicMinF(float* a, float v) {
    if (v >= 0.f) atomicMin((int*)a, __float_as_int(v));
    else          atomicMax((unsigned int*)a, __float_as_uint(v));
}
__device__ __forceinline__ void atomicMaxF(float* a, float v) {
    if (v >= 0.f) atomicMax((int*)a, __float_as_int(v));
    else          atomicMin((unsigned int*)a, __float_as_uint(v));
}

__device__ __forceinline__ uint32_t smem_u32(const void* p) {
    uint32_t a;
    asm("{ .reg .u64 t; cvta.to.shared.u64 t, %1; cvt.u32.u64 %0, t; }" : "=r"(a) : "l"(p));
    return a;
}
__device__ __forceinline__ void ldsm_x4(uint32_t* r, uint32_t addr) {
    asm volatile("ldmatrix.sync.aligned.m8n8.x4.shared.b16 {%0,%1,%2,%3}, [%4];"
                 : "=r"(r[0]), "=r"(r[1]), "=r"(r[2]), "=r"(r[3]) : "r"(addr));
}
__device__ __forceinline__ void mma_bf16(float* d, const uint32_t* a, const uint32_t* b) {
    asm volatile(
        "mma.sync.aligned.m16n8k16.row.col.f32.bf16.bf16.f32 "
        "{%0,%1,%2,%3}, {%4,%5,%6,%7}, {%8,%9}, {%0,%1,%2,%3};"
        : "+f"(d[0]), "+f"(d[1]), "+f"(d[2]), "+f"(d[3])
        : "r"(a[0]), "r"(a[1]), "r"(a[2]), "r"(a[3]), "r"(b[0]), "r"(b[1]));
}

__global__ void tl_init() {
    int i = blockIdx.x * 256 + threadIdx.x;
    if (i < M) { g_pos[i] = f_inf(); g_neg[i] = f_ninf(); }
}

__global__ __launch_bounds__(256)
void tl_gemm(const float* __restrict__ A, const float* __restrict__ B,
             const int* __restrict__ targets, const int* __restrict__ idxv,
             const int* __restrict__ labels)
{
    __shared__ __nv_bfloat16 As[2][BM][LDS_STRIDE];
    __shared__ __nv_bfloat16 Bs[2][BN][LDS_STRIDE];
    __shared__ int   sLab[BN];
    __shared__ int   sT[BM];
    __shared__ int   sI[BM];
    __shared__ float sPos[BM];
    __shared__ float sNeg[BM];

    const int tid  = threadIdx.x;
    const int lane = tid & 31;
    const int wid  = tid >> 5;
    const int rowBase = blockIdx.y * BM;
    const int colBase = blockIdx.x * BN;

    // warp layout: 2 (m) x 4 (n); warp tile 64 x 32
    const int warp_m = (wid >> 2) * 64;
    const int warp_n = (wid & 3) * 32;

    for (int i = tid; i < BN; i += 256) sLab[i] = labels[colBase + i];
    for (int i = tid; i < BM; i += 256) {
        sT[i] = targets[rowBase + i];
        sI[i] = idxv[rowBase + i];
        sPos[i] = f_inf(); sNeg[i] = f_ninf();
    }

    // gmem loader mapping: r = tid/8 (+32*i), c = (tid%8)*4
    const int ldr = tid >> 3;
    const int ldc = (tid & 7) * 4;

    // ldmatrix smem addresses (buffer 0); buffer stride in bytes
    constexpr uint32_t ABUF = BM * LDS_STRIDE * 2;   // 10240
    constexpr uint32_t BBUF = BN * LDS_STRIDE * 2;
    uint32_t aAddr[4], bAddr[2];
#pragma unroll
    for (int mi = 0; mi < 4; ++mi)
        aAddr[mi] = smem_u32(&As[0][warp_m + mi * 16 + (lane & 15)][(lane >> 4) * 8]);
#pragma unroll
    for (int g = 0; g < 2; ++g)
        bAddr[g] = smem_u32(&Bs[0][warp_n + g * 16 + (lane & 7) + ((lane >> 4) * 8)]
                                  [((lane >> 3) & 1) * 8]);

    float acc[4][4][4] = {};   // [mi][ni][frag]

    float4 stgA[4], stgB[4];
    auto ldg_chunk = [&](int c) {
        const int kb = c * BK;
#pragma unroll
        for (int i = 0; i < 4; ++i) {
            stgA[i] = *reinterpret_cast<const float4*>(
                &A[(size_t)(rowBase + ldr + 32 * i) * K + kb + ldc]);
            stgB[i] = *reinterpret_cast<const float4*>(
                &B[(size_t)(colBase + ldr + 32 * i) * K + kb + ldc]);
        }
    };
    auto sts_chunk = [&](int buf) {
#pragma unroll
        for (int i = 0; i < 4; ++i) {
            __nv_bfloat162 a0 = __float22bfloat162_rn(make_float2(stgA[i].x, stgA[i].y));
            __nv_bfloat162 a1 = __float22bfloat162_rn(make_float2(stgA[i].z, stgA[i].w));
            *reinterpret_cast<uint2*>(&As[buf][ldr + 32 * i][ldc]) =
                make_uint2(*(uint32_t*)&a0, *(uint32_t*)&a1);
            __nv_bfloat162 b0 = __float22bfloat162_rn(make_float2(stgB[i].x, stgB[i].y));
            __nv_bfloat162 b1 = __float22bfloat162_rn(make_float2(stgB[i].z, stgB[i].w));
            *reinterpret_cast<uint2*>(&Bs[buf][ldr + 32 * i][ldc]) =
                make_uint2(*(uint32_t*)&b0, *(uint32_t*)&b1);
        }
    };

    ldg_chunk(0);
    sts_chunk(0);
    __syncthreads();

    for (int c = 0; c < NCH; ++c) {
        const int buf = c & 1;
        if (c + 1 < NCH) ldg_chunk(c + 1);

        const uint32_t aOff = buf ? ABUF : 0u;
        const uint32_t bOff = buf ? BBUF : 0u;
#pragma unroll
        for (int ks = 0; ks < 2; ++ks) {
            uint32_t af[4][4], bf[2][4];
#pragma unroll
            for (int mi = 0; mi < 4; ++mi) ldsm_x4(af[mi], aAddr[mi] + aOff + ks * 32);
#pragma unroll
            for (int g = 0; g < 2; ++g)    ldsm_x4(bf[g],  bAddr[g]  + bOff + ks * 32);
#pragma unroll
            for (int mi = 0; mi < 4; ++mi)
#pragma unroll
                for (int ni = 0; ni < 4; ++ni)
                    mma_bf16(acc[mi][ni], af[mi], &bf[ni >> 1][(ni & 1) * 2]);
        }

        if (c + 1 < NCH) sts_chunk(buf ^ 1);
        __syncthreads();
    }

    // Epilogue: masked min/max. Thread owns rows (warp_m + mi*16 + h*8 + lane/4),
    // cols (warp_n + ni*8 + (lane%4)*2 + j).
    const int lq = lane >> 2;
    const int lr = (lane & 3) * 2;
#pragma unroll
    for (int mi = 0; mi < 4; ++mi) {
#pragma unroll
        for (int h = 0; h < 2; ++h) {
            const int rloc = warp_m + mi * 16 + h * 8 + lq;
            const int tg = sT[rloc];
            const int ix = sI[rloc];
            float pmin = f_inf(), nmax = f_ninf();
#pragma unroll
            for (int ni = 0; ni < 4; ++ni) {
#pragma unroll
                for (int j = 0; j < 2; ++j) {
                    const int cloc = warp_n + ni * 8 + lr + j;
                    const float v = acc[mi][ni][h * 2 + j];
                    if (sLab[cloc] == tg) {
                        if (colBase + cloc != ix) pmin = fminf(pmin, v);
                    } else {
                        nmax = fmaxf(nmax, v);
                    }
                }
            }
            atomicMinF(&sPos[rloc], pmin);
            atomicMaxF(&sNeg[rloc], nmax);
        }
    }
    __syncthreads();

    for (int i = tid; i < BM; i += 256) {
        const float p = sPos[i], q = sNeg[i];
        if (p <  f_inf())  atomicMinF(&g_pos[rowBase + i], p);
        if (q > f_ninf())  atomicMaxF(&g_neg[rowBase + i], q);
    }
}

__global__ void tl_final(float* __restrict__ out) {
    __shared__ float red[32];
    const int i = threadIdx.x;
    float l = fmaxf(g_neg[i] - g_pos[i] + MARGIN, 0.0f);
#pragma unroll
    for (int o = 16; o > 0; o >>= 1) l += __shfl_xor_sync(0xffffffffu, l, o);
    if ((i & 31) == 0) red[i >> 5] = l;
    __syncthreads();
    if (i < 32) {
        float s = red[i];
#pragma unroll
        for (int o = 16; o > 0; o >>= 1) s += __shfl_xor_sync(0xffffffffu, s, o);
        if (i == 0) out[0] = s * (1.0f / (float)M);
    }
}

extern "C" void kernel_launch(void* const* d_in, const int* in_sizes, int n_in,
                              void* d_out, int out_size) {
    const float* A       = (const float*)d_in[0];
    const float* B       = (const float*)d_in[1];
    const int*   targets = (const int*)  d_in[2];
    const int*   idxv    = (const int*)  d_in[3];
    const int*   labels  = (const int*)  d_in[4];
    float*       out     = (float*)d_out;

    tl_init<<<(M + 255) / 256, 256>>>();
    dim3 grid(N / BN, M / BM);   // 256 x 8 = 2048 CTAs
    tl_gemm<<<grid, 256>>>(A, B, targets, idxv, labels);
    tl_final<<<1, M>>>(out);
}